// round 3
// baseline (speedup 1.0000x reference)
#include <cuda_runtime.h>
#include <cstdint>
#include <cmath>

// Problem constants (fixed by the dataset)
#define T_TOK 1024
#define H_DIM 2048
#define I_DIM 768
#define E_NUM 8
#define K_TOP 2
#define NROWS (T_TOK * K_TOP)      // 2048 permuted rows

// Tiling
#define BM 128
#define BN 128                      // gemm2 N-tile; gemm1 uses 64 gate + 64 up
#define BK 16
#define MAX_TILES 24                // sum_e ceil(cnt_e/128) <= 16 + 8

// ---------------- scratch (no allocations allowed) ----------------
__device__ int   g_row_src[NROWS];        // sorted-position -> flat (t*K + k)
__device__ int   g_pos[NROWS];            // flat (t*K+k) -> sorted-position
__device__ int   g_tile_expert[MAX_TILES];
__device__ int   g_tile_row[MAX_TILES];
__device__ int   g_tile_end[MAX_TILES];
__device__ int   g_num_tiles;
__device__ float g_act[NROWS * I_DIM];    // swiglu output [2048, 768]
__device__ float g_fc2[NROWS * H_DIM];    // fc2 output    [2048, 2048]

// ---------------- f32x2 helpers ----------------
__device__ __forceinline__ void ffma2(uint64_t& d, uint64_t a, uint64_t b) {
    asm("fma.rn.f32x2 %0, %1, %2, %0;" : "+l"(d) : "l"(a), "l"(b));
}
__device__ __forceinline__ uint64_t dup2(float x) {
    uint32_t b = __float_as_uint(x);
    return ((uint64_t)b << 32) | (uint64_t)b;
}
__device__ __forceinline__ uint64_t pack2(float lo, float hi) {
    return ((uint64_t)__float_as_uint(hi) << 32) | (uint64_t)__float_as_uint(lo);
}
__device__ __forceinline__ float lo2(uint64_t v) { return __uint_as_float((uint32_t)v); }
__device__ __forceinline__ float hi2(uint64_t v) { return __uint_as_float((uint32_t)(v >> 32)); }

// ---------------- setup: counting sort by expert + tile descriptors ----------------
__global__ void setup_kernel(const int* __restrict__ sel) {
    __shared__ int cnt[E_NUM];
    __shared__ int run[E_NUM];
    int tid = threadIdx.x;
    if (tid < E_NUM) cnt[tid] = 0;
    __syncthreads();
    for (int i = tid; i < NROWS; i += blockDim.x)
        atomicAdd(&cnt[sel[i]], 1);
    __syncthreads();
    if (tid == 0) {
        int s = 0, nt = 0;
        for (int e = 0; e < E_NUM; e++) {
            run[e] = s;
            int c = cnt[e];
            for (int r = 0; r < c; r += BM) {
                g_tile_expert[nt] = e;
                g_tile_row[nt]    = s + r;
                g_tile_end[nt]    = s + c;
                nt++;
            }
            s += c;
        }
        g_num_tiles = nt;
    }
    __syncthreads();
    for (int i = tid; i < NROWS; i += blockDim.x) {
        int e = sel[i];
        int p = atomicAdd(&run[e], 1);
        g_row_src[p] = i;
        g_pos[i] = p;
    }
}

// ---------------- GEMM1: act = swiglu( X_gather @ W1[e] ) ----------------
// Block tile: 128 rows x (64 gate cols + matching 64 up cols), 8x(4+4) per thread.
__global__ void __launch_bounds__(256, 2)
gemm1_kernel(const float* __restrict__ x, const float* __restrict__ w1) {
    int mt = blockIdx.x;
    if (mt >= g_num_tiles) return;
    int e    = g_tile_expert[mt];
    int row0 = g_tile_row[mt];
    int rend = g_tile_end[mt];
    int col0 = blockIdx.y * 64;                 // 0 .. I_DIM-64

    const float* W = w1 + (size_t)e * H_DIM * (2 * I_DIM);

    __shared__ float As[BK][BM];
    __shared__ float Ba[BK][64];
    __shared__ float Bb[BK][64];
    __shared__ int   s_tok[BM];

    int tid = threadIdx.x;
    if (tid < BM) {
        int r = row0 + tid;
        s_tok[tid] = (r < rend) ? (g_row_src[r] / K_TOP) : -1;
    }
    __syncthreads();

    int ty = tid >> 4;              // 0..15 : rows ty*4..+3 and ty*4+64..+3
    int tx = tid & 15;              // 0..15 : cols tx*4..+3 (both gate and up)

    // A load mapping: ar = tid/2 (row), ak = (tid&1)*8 (k-offset), 2 float4 each
    int ar = tid >> 1;
    int ak = (tid & 1) * 8;
    // B load mapping: bkk = tid/16, bc = (tid%16)*4, one gate + one up float4
    int bkk = tid >> 4;
    int bc  = (tid & 15) * 4;

    uint64_t accG[8][2] = {}, accU[8][2] = {};

    for (int k0 = 0; k0 < H_DIM; k0 += BK) {
        // ---- A: 128x16 gathered rows ----
        {
            int tok = s_tok[ar];
            float4 v0 = make_float4(0.f,0.f,0.f,0.f), v1 = v0;
            if (tok >= 0) {
                const float* xp = &x[(size_t)tok * H_DIM + k0 + ak];
                v0 = *reinterpret_cast<const float4*>(xp);
                v1 = *reinterpret_cast<const float4*>(xp + 4);
            }
            As[ak + 0][ar] = v0.x; As[ak + 1][ar] = v0.y;
            As[ak + 2][ar] = v0.z; As[ak + 3][ar] = v0.w;
            As[ak + 4][ar] = v1.x; As[ak + 5][ar] = v1.y;
            As[ak + 6][ar] = v1.z; As[ak + 7][ar] = v1.w;
        }
        // ---- B: gate 16x64 + up 16x64 ----
        {
            const float* wr = W + (size_t)(k0 + bkk) * (2 * I_DIM) + col0 + bc;
            *reinterpret_cast<float4*>(&Ba[bkk][bc]) = *reinterpret_cast<const float4*>(wr);
            *reinterpret_cast<float4*>(&Bb[bkk][bc]) = *reinterpret_cast<const float4*>(wr + I_DIM);
        }
        __syncthreads();

        #pragma unroll
        for (int kk = 0; kk < BK; kk++) {
            float4 a0 = *reinterpret_cast<const float4*>(&As[kk][ty * 4]);
            float4 a1 = *reinterpret_cast<const float4*>(&As[kk][ty * 4 + 64]);
            float4 g4 = *reinterpret_cast<const float4*>(&Ba[kk][tx * 4]);
            float4 u4 = *reinterpret_cast<const float4*>(&Bb[kk][tx * 4]);
            uint64_t aa[8] = { dup2(a0.x), dup2(a0.y), dup2(a0.z), dup2(a0.w),
                               dup2(a1.x), dup2(a1.y), dup2(a1.z), dup2(a1.w) };
            uint64_t gg[2] = { pack2(g4.x, g4.y), pack2(g4.z, g4.w) };
            uint64_t uu[2] = { pack2(u4.x, u4.y), pack2(u4.z, u4.w) };
            #pragma unroll
            for (int i = 0; i < 8; i++) {
                ffma2(accG[i][0], aa[i], gg[0]);
                ffma2(accG[i][1], aa[i], gg[1]);
                ffma2(accU[i][0], aa[i], uu[0]);
                ffma2(accU[i][1], aa[i], uu[1]);
            }
        }
        __syncthreads();
    }

    // epilogue: swiglu, store to g_act
    #pragma unroll
    for (int i = 0; i < 8; i++) {
        int r = row0 + ty * 4 + (i & 3) + (i >> 2) * 64;
        if (r < rend) {
            float g[4] = { lo2(accG[i][0]), hi2(accG[i][0]), lo2(accG[i][1]), hi2(accG[i][1]) };
            float u[4] = { lo2(accU[i][0]), hi2(accU[i][0]), lo2(accU[i][1]), hi2(accU[i][1]) };
            float4 o;
            float* op = reinterpret_cast<float*>(&o);
            #pragma unroll
            for (int j = 0; j < 4; j++) {
                float sig = 1.0f / (1.0f + __expf(-g[j]));
                op[j] = g[j] * sig * u[j];
            }
            *reinterpret_cast<float4*>(&g_act[(size_t)r * I_DIM + col0 + tx * 4]) = o;
        }
    }
}

// ---------------- GEMM2: fc2 = act @ W2[e]  (rows already sorted; no gather) ----------------
__global__ void __launch_bounds__(256, 2)
gemm2_kernel(const float* __restrict__ w2) {
    int mt = blockIdx.x;
    if (mt >= g_num_tiles) return;
    int e    = g_tile_expert[mt];
    int row0 = g_tile_row[mt];
    int rend = g_tile_end[mt];
    int col0 = blockIdx.y * BN;

    const float* W = w2 + (size_t)e * I_DIM * H_DIM;

    __shared__ float As[BK][BM];
    __shared__ float Bs[BK][BN];

    int tid = threadIdx.x;
    int ty = tid >> 4;              // rows ty*4 and ty*4+64
    int tx = tid & 15;              // cols tx*4 and tx*4+64

    int ar = tid >> 1;
    int ak = (tid & 1) * 8;
    int bkk = tid >> 4;
    int bc  = (tid & 15) * 4;

    uint64_t acc[8][4] = {};

    for (int k0 = 0; k0 < I_DIM; k0 += BK) {
        {
            int rr = row0 + ar;
            if (rr >= NROWS) rr = NROWS - 1;      // clamp (values discarded by epilogue guard)
            const float* ap = &g_act[(size_t)rr * I_DIM + k0 + ak];
            float4 v0 = *reinterpret_cast<const float4*>(ap);
            float4 v1 = *reinterpret_cast<const float4*>(ap + 4);
            As[ak + 0][ar] = v0.x; As[ak + 1][ar] = v0.y;
            As[ak + 2][ar] = v0.z; As[ak + 3][ar] = v0.w;
            As[ak + 4][ar] = v1.x; As[ak + 5][ar] = v1.y;
            As[ak + 6][ar] = v1.z; As[ak + 7][ar] = v1.w;
        }
        {
            const float* wr = W + (size_t)(k0 + bkk) * H_DIM + col0 + bc;
            *reinterpret_cast<float4*>(&Bs[bkk][bc]) = *reinterpret_cast<const float4*>(wr);
            *reinterpret_cast<float4*>(&Bs[bkk][bc + 64]) = *reinterpret_cast<const float4*>(wr + 64);
        }
        __syncthreads();

        #pragma unroll
        for (int kk = 0; kk < BK; kk++) {
            float4 a0 = *reinterpret_cast<const float4*>(&As[kk][ty * 4]);
            float4 a1 = *reinterpret_cast<const float4*>(&As[kk][ty * 4 + 64]);
            float4 b0 = *reinterpret_cast<const float4*>(&Bs[kk][tx * 4]);
            float4 b1 = *reinterpret_cast<const float4*>(&Bs[kk][tx * 4 + 64]);
            uint64_t aa[8] = { dup2(a0.x), dup2(a0.y), dup2(a0.z), dup2(a0.w),
                               dup2(a1.x), dup2(a1.y), dup2(a1.z), dup2(a1.w) };
            uint64_t bb[4] = { pack2(b0.x, b0.y), pack2(b0.z, b0.w),
                               pack2(b1.x, b1.y), pack2(b1.z, b1.w) };
            #pragma unroll
            for (int i = 0; i < 8; i++)
                #pragma unroll
                for (int j = 0; j < 4; j++)
                    ffma2(acc[i][j], aa[i], bb[j]);
        }
        __syncthreads();
    }

    #pragma unroll
    for (int i = 0; i < 8; i++) {
        int r = row0 + ty * 4 + (i & 3) + (i >> 2) * 64;
        if (r < rend) {
            float* orow = &g_fc2[(size_t)r * H_DIM + col0];
            float4 o0, o1;
            o0.x = lo2(acc[i][0]); o0.y = hi2(acc[i][0]);
            o0.z = lo2(acc[i][1]); o0.w = hi2(acc[i][1]);
            o1.x = lo2(acc[i][2]); o1.y = hi2(acc[i][2]);
            o1.z = lo2(acc[i][3]); o1.w = hi2(acc[i][3]);
            *reinterpret_cast<float4*>(&orow[tx * 4])      = o0;
            *reinterpret_cast<float4*>(&orow[tx * 4 + 64]) = o1;
        }
    }
}

// ---------------- combine: out[t] = rw[t,0]*fc2[pos(2t)] + rw[t,1]*fc2[pos(2t+1)] ----------------
__global__ void __launch_bounds__(256)
combine_kernel(const float* __restrict__ rw, float* __restrict__ out) {
    int i = blockIdx.x * blockDim.x + threadIdx.x;     // 0 .. T*H/4-1
    if (i >= T_TOK * (H_DIM / 4)) return;
    int t  = i >> 9;                                    // H/4 = 512
    int h4 = i & 511;
    int p0 = g_pos[2 * t];
    int p1 = g_pos[2 * t + 1];
    float w0 = rw[2 * t];
    float w1 = rw[2 * t + 1];
    float4 v0 = *reinterpret_cast<const float4*>(&g_fc2[(size_t)p0 * H_DIM + h4 * 4]);
    float4 v1 = *reinterpret_cast<const float4*>(&g_fc2[(size_t)p1 * H_DIM + h4 * 4]);
    float4 o;
    o.x = w0 * v0.x + w1 * v1.x;
    o.y = w0 * v0.y + w1 * v1.y;
    o.z = w0 * v0.z + w1 * v1.z;
    o.w = w0 * v0.w + w1 * v1.w;
    reinterpret_cast<float4*>(out)[i] = o;
}

// ---------------- launch ----------------
extern "C" void kernel_launch(void* const* d_in, const int* in_sizes, int n_in,
                              void* d_out, int out_size) {
    const float* x   = (const float*)d_in[0];   // hidden_states [T, H]
    const float* rw  = (const float*)d_in[1];   // routing_weights [T, K]
    const float* w1  = (const float*)d_in[2];   // gate_up_proj [E, H, 2I]
    const float* w2  = (const float*)d_in[3];   // down_proj   [E, I, H]
    const int*   sel = (const int*)d_in[4];     // selected_experts [T, K]
    float* out = (float*)d_out;                 // [T, H] fp32

    setup_kernel<<<1, 256>>>(sel);
    gemm1_kernel<<<dim3(MAX_TILES, I_DIM / 64), 256>>>(x, w1);
    gemm2_kernel<<<dim3(MAX_TILES, H_DIM / BN), 256>>>(w2);
    combine_kernel<<<(T_TOK * H_DIM / 4 + 255) / 256, 256>>>(rw, out);
}

// round 5
// speedup vs baseline: 3.0839x; 3.0839x over previous
#include <cuda_runtime.h>
#include <cstdint>
#include <cmath>

// Problem constants (fixed by the dataset)
#define T_TOK 1024
#define H_DIM 2048
#define I_DIM 768
#define E_NUM 8
#define K_TOP 2
#define NROWS (T_TOK * K_TOP)      // 2048 permuted rows

#define BM 128
#define MAX_TILES 24

// ---------------- scratch (no allocations allowed) ----------------
__device__ int   g_row_src[NROWS];
__device__ int   g_pos[NROWS];
__device__ int   g_tile_expert[MAX_TILES];
__device__ int   g_tile_row[MAX_TILES];
__device__ int   g_tile_end[MAX_TILES];
__device__ int   g_num_tiles;
__device__ float g_act[NROWS * I_DIM];
__device__ float g_fc2[NROWS * H_DIM];

// ---------------- PTX helpers (all sm_80-level, no 'a' features) ----------------
__device__ __forceinline__ uint32_t s2u(const void* p) {
    uint32_t a;
    asm("{ .reg .u64 t; cvta.to.shared.u64 t, %1; cvt.u32.u64 %0, t; }" : "=r"(a) : "l"(p));
    return a;
}
__device__ __forceinline__ void cp16(uint32_t dst, const void* src, uint32_t sz) {
    asm volatile("cp.async.cg.shared.global [%0], [%1], 16, %2;" :: "r"(dst), "l"(src), "r"(sz));
}
__device__ __forceinline__ void cp_commit() { asm volatile("cp.async.commit_group;" ::: "memory"); }
template<int N> __device__ __forceinline__ void cp_wait() {
    asm volatile("cp.async.wait_group %0;" :: "n"(N) : "memory");
}
__device__ __forceinline__ void ldsm4(uint32_t r[4], uint32_t addr) {
    asm volatile("ldmatrix.sync.aligned.m8n8.x4.shared.b16 {%0,%1,%2,%3}, [%4];"
        : "=r"(r[0]), "=r"(r[1]), "=r"(r[2]), "=r"(r[3]) : "r"(addr));
}
__device__ __forceinline__ uint32_t f2tf_u(uint32_t x) {
    uint32_t r;
    asm("cvt.rna.tf32.f32 %0, %1;" : "=r"(r) : "f"(__uint_as_float(x)));
    return r;
}
__device__ __forceinline__ uint32_t f2tf_f(float x) {
    uint32_t r;
    asm("cvt.rna.tf32.f32 %0, %1;" : "=r"(r) : "f"(x));
    return r;
}
__device__ __forceinline__ void mma8(float* c, const uint32_t* a, uint32_t b0, uint32_t b1) {
    asm volatile(
        "mma.sync.aligned.m16n8k8.row.col.f32.tf32.tf32.f32 "
        "{%0,%1,%2,%3}, {%4,%5,%6,%7}, {%8,%9}, {%0,%1,%2,%3};"
        : "+f"(c[0]), "+f"(c[1]), "+f"(c[2]), "+f"(c[3])
        : "r"(a[0]), "r"(a[1]), "r"(a[2]), "r"(a[3]), "r"(b0), "r"(b1));
}

// SMEM layout (byte offsets into dynamic smem)
// [0,512)  s_tok   [1024 ...) two stages of {A 16KB, B 16.5KB}
#define STAGE_BYTES 33280
#define OFF_A(b) (1024 + (b) * STAGE_BYTES)
#define OFF_B(b) (OFF_A(b) + 16384)
#define SMEM_TOTAL 68608            // epilogue Es (128x132 f32) reuses [1024, 68608)

// ---------------- setup ----------------
__global__ void setup_kernel(const int* __restrict__ sel) {
    __shared__ int cnt[E_NUM];
    __shared__ int run[E_NUM];
    int tid = threadIdx.x;
    if (tid < E_NUM) cnt[tid] = 0;
    __syncthreads();
    for (int i = tid; i < NROWS; i += blockDim.x)
        atomicAdd(&cnt[sel[i]], 1);
    __syncthreads();
    if (tid == 0) {
        int s = 0, nt = 0;
        for (int e = 0; e < E_NUM; e++) {
            run[e] = s;
            int c = cnt[e];
            for (int r = 0; r < c; r += BM) {
                g_tile_expert[nt] = e;
                g_tile_row[nt]    = s + r;
                g_tile_end[nt]    = s + c;
                nt++;
            }
            s += c;
        }
        g_num_tiles = nt;
    }
    __syncthreads();
    for (int i = tid; i < NROWS; i += blockDim.x) {
        int e = sel[i];
        int p = atomicAdd(&run[e], 1);
        g_row_src[p] = i;
        g_pos[i] = p;
    }
}

// ---------------- GEMM1: act = swiglu( X_gather @ W1[e] ), tf32 mma.sync ----------------
// Block: 128 rows x (gate 64 + up 64 cols of fc1).
__global__ void __launch_bounds__(256, 2)
gemm1_kernel(const float* __restrict__ x, const float* __restrict__ w1) {
    extern __shared__ char smem[];
    uint32_t sb = s2u(smem);
    int mt = blockIdx.x;
    if (mt >= g_num_tiles) return;
    int e = g_tile_expert[mt], row0 = g_tile_row[mt], rend = g_tile_end[mt];
    int col0g = blockIdx.y * 64;

    int tid = threadIdx.x, lane = tid & 31, wid = tid >> 5;
    int warpM = wid >> 2, warpN = wid & 3;
    int gid = lane >> 2, tig = lane & 3;

    int* s_tok = (int*)smem;
    if (tid < 128) {
        int r = row0 + tid;
        s_tok[tid] = (r < rend) ? (g_row_src[r] / K_TOP) : -1;
    }
    __syncthreads();

    const float* W = w1 + (size_t)e * H_DIM * (2 * I_DIM);
    int am = tid >> 1;
    int tokm = s_tok[am];
    const float* asrc = x + (size_t)(tokm < 0 ? 0 : tokm) * H_DIM;
    uint32_t asz = (tokm < 0) ? 0u : 16u;
    int ac0 = (tid & 1) * 4;
    int akey = am & 7;

    auto load_chunk = [&](int ci, int buf) {
        int k0 = ci * 32;
        uint32_t Ab = sb + OFF_A(buf);
        #pragma unroll
        for (int c = 0; c < 4; c++) {
            int cc = ac0 + c;
            cp16(Ab + am * 128 + ((cc ^ akey) << 4), asrc + k0 + cc * 4, asz);
        }
        uint32_t Bb = sb + OFF_B(buf);
        #pragma unroll
        for (int it = 0; it < 4; it++) {
            int q = tid + it * 256;
            int k = q >> 5, c16 = q & 31, n = c16 * 4;
            const float* src = (n < 64)
                ? W + (size_t)(k0 + k) * (2 * I_DIM) + col0g + n
                : W + (size_t)(k0 + k) * (2 * I_DIM) + I_DIM + col0g + (n - 64);
            cp16(Bb + k * 528 + n * 4, src, 16);
        }
        cp_commit();
    };

    int mlane = lane & 15, extra = lane >> 4, key = lane & 7;
    int boff = tig * 132 + warpN * 32 + gid;

    float acc[4][4][4] = {};
    const int NC = H_DIM / 32;   // 64
    load_chunk(0, 0);
    for (int i = 0; i < NC; i++) {
        int b = i & 1;
        if (i + 1 < NC) { load_chunk(i + 1, b ^ 1); cp_wait<1>(); }
        else           { cp_wait<0>(); }
        __syncthreads();

        uint32_t Ab = sb + OFF_A(b);
        const float* Bsp = (const float*)(smem + OFF_B(b));
        #pragma unroll
        for (int ks = 0; ks < 4; ks++) {
            uint32_t a[4][4];
            #pragma unroll
            for (int mi = 0; mi < 4; mi++) {
                uint32_t addr = Ab + (uint32_t)((warpM * 64 + mi * 16 + mlane) * 128
                              + ((((ks << 1) | extra) ^ key) << 4));
                ldsm4(a[mi], addr);
                #pragma unroll
                for (int q = 0; q < 4; q++) a[mi][q] = f2tf_u(a[mi][q]);
            }
            #pragma unroll
            for (int j = 0; j < 4; j++) {
                uint32_t b0 = f2tf_f(Bsp[boff + ks * 1056 + j * 8]);
                uint32_t b1 = f2tf_f(Bsp[boff + ks * 1056 + j * 8 + 528]);
                #pragma unroll
                for (int mi = 0; mi < 4; mi++)
                    mma8(acc[mi][j], a[mi], b0, b1);
            }
        }
        __syncthreads();
    }

    // epilogue: frags -> smem, then swiglu -> g_act
    float* Es = (float*)(smem + 1024);
    #pragma unroll
    for (int mi = 0; mi < 4; mi++)
        #pragma unroll
        for (int j = 0; j < 4; j++) {
            int row = warpM * 64 + mi * 16 + gid;
            int col = warpN * 32 + j * 8 + 2 * tig;
            *(float2*)&Es[row * 132 + col]       = make_float2(acc[mi][j][0], acc[mi][j][1]);
            *(float2*)&Es[(row + 8) * 132 + col] = make_float2(acc[mi][j][2], acc[mi][j][3]);
        }
    __syncthreads();

    int rr = tid >> 1;
    int r  = row0 + rr;
    int cb = (tid & 1) * 32;
    if (r < rend) {
        float* dst = g_act + (size_t)r * I_DIM + col0g + cb;
        #pragma unroll
        for (int jj = 0; jj < 32; jj += 4) {
            float4 gv = *(float4*)&Es[rr * 132 + cb + jj];
            float4 uv = *(float4*)&Es[rr * 132 + 64 + cb + jj];
            float4 o;
            o.x = gv.x * (1.0f / (1.0f + __expf(-gv.x))) * uv.x;
            o.y = gv.y * (1.0f / (1.0f + __expf(-gv.y))) * uv.y;
            o.z = gv.z * (1.0f / (1.0f + __expf(-gv.z))) * uv.z;
            o.w = gv.w * (1.0f / (1.0f + __expf(-gv.w))) * uv.w;
            *(float4*)(dst + jj) = o;
        }
    }
}

// ---------------- GEMM2: fc2 = act @ W2[e], tf32 mma.sync ----------------
// Block: 128 rows x 128 cols.
__global__ void __launch_bounds__(256, 2)
gemm2_kernel(const float* __restrict__ w2) {
    extern __shared__ char smem[];
    uint32_t sb = s2u(smem);
    int mt = blockIdx.x;
    if (mt >= g_num_tiles) return;
    int e = g_tile_expert[mt], row0 = g_tile_row[mt], rend = g_tile_end[mt];
    int col0 = blockIdx.y * 128;

    int tid = threadIdx.x, lane = tid & 31, wid = tid >> 5;
    int warpM = wid >> 2, warpN = wid & 3;
    int gid = lane >> 2, tig = lane & 3;

    const float* W = w2 + (size_t)e * I_DIM * H_DIM;
    int am = tid >> 1;
    int rrow = row0 + am; if (rrow >= NROWS) rrow = NROWS - 1;   // clamp; masked later
    const float* asrc = g_act + (size_t)rrow * I_DIM;
    int ac0 = (tid & 1) * 4;
    int akey = am & 7;

    auto load_chunk = [&](int ci, int buf) {
        int k0 = ci * 32;
        uint32_t Ab = sb + OFF_A(buf);
        #pragma unroll
        for (int c = 0; c < 4; c++) {
            int cc = ac0 + c;
            cp16(Ab + am * 128 + ((cc ^ akey) << 4), asrc + k0 + cc * 4, 16);
        }
        uint32_t Bb = sb + OFF_B(buf);
        #pragma unroll
        for (int it = 0; it < 4; it++) {
            int q = tid + it * 256;
            int k = q >> 5, c16 = q & 31, n = c16 * 4;
            cp16(Bb + k * 528 + n * 4, W + (size_t)(k0 + k) * H_DIM + col0 + n, 16);
        }
        cp_commit();
    };

    int mlane = lane & 15, extra = lane >> 4, key = lane & 7;
    int boff = tig * 132 + warpN * 32 + gid;

    float acc[4][4][4] = {};
    const int NC = I_DIM / 32;   // 24
    load_chunk(0, 0);
    for (int i = 0; i < NC; i++) {
        int b = i & 1;
        if (i + 1 < NC) { load_chunk(i + 1, b ^ 1); cp_wait<1>(); }
        else           { cp_wait<0>(); }
        __syncthreads();

        uint32_t Ab = sb + OFF_A(b);
        const float* Bsp = (const float*)(smem + OFF_B(b));
        #pragma unroll
        for (int ks = 0; ks < 4; ks++) {
            uint32_t a[4][4];
            #pragma unroll
            for (int mi = 0; mi < 4; mi++) {
                uint32_t addr = Ab + (uint32_t)((warpM * 64 + mi * 16 + mlane) * 128
                              + ((((ks << 1) | extra) ^ key) << 4));
                ldsm4(a[mi], addr);
                #pragma unroll
                for (int q = 0; q < 4; q++) a[mi][q] = f2tf_u(a[mi][q]);
            }
            #pragma unroll
            for (int j = 0; j < 4; j++) {
                uint32_t b0 = f2tf_f(Bsp[boff + ks * 1056 + j * 8]);
                uint32_t b1 = f2tf_f(Bsp[boff + ks * 1056 + j * 8 + 528]);
                #pragma unroll
                for (int mi = 0; mi < 4; mi++)
                    mma8(acc[mi][j], a[mi], b0, b1);
            }
        }
        __syncthreads();
    }

    // epilogue: direct to g_fc2
    #pragma unroll
    for (int mi = 0; mi < 4; mi++) {
        int row = row0 + warpM * 64 + mi * 16 + gid;
        #pragma unroll
        for (int j = 0; j < 4; j++) {
            int col = col0 + warpN * 32 + j * 8 + 2 * tig;
            if (row < rend)
                *(float2*)&g_fc2[(size_t)row * H_DIM + col] =
                    make_float2(acc[mi][j][0], acc[mi][j][1]);
            if (row + 8 < rend)
                *(float2*)&g_fc2[(size_t)(row + 8) * H_DIM + col] =
                    make_float2(acc[mi][j][2], acc[mi][j][3]);
        }
    }
}

// ---------------- combine ----------------
__global__ void __launch_bounds__(256)
combine_kernel(const float* __restrict__ rw, float* __restrict__ out) {
    int i = blockIdx.x * blockDim.x + threadIdx.x;
    if (i >= T_TOK * (H_DIM / 4)) return;
    int t  = i >> 9;
    int h4 = i & 511;
    int p0 = g_pos[2 * t];
    int p1 = g_pos[2 * t + 1];
    float w0 = rw[2 * t];
    float w1 = rw[2 * t + 1];
    float4 v0 = *reinterpret_cast<const float4*>(&g_fc2[(size_t)p0 * H_DIM + h4 * 4]);
    float4 v1 = *reinterpret_cast<const float4*>(&g_fc2[(size_t)p1 * H_DIM + h4 * 4]);
    float4 o;
    o.x = w0 * v0.x + w1 * v1.x;
    o.y = w0 * v0.y + w1 * v1.y;
    o.z = w0 * v0.z + w1 * v1.z;
    o.w = w0 * v0.w + w1 * v1.w;
    reinterpret_cast<float4*>(out)[i] = o;
}

// ---------------- launch ----------------
extern "C" void kernel_launch(void* const* d_in, const int* in_sizes, int n_in,
                              void* d_out, int out_size) {
    const float* x   = (const float*)d_in[0];   // hidden_states [T, H]
    const float* rw  = (const float*)d_in[1];   // routing_weights [T, K]
    const float* w1  = (const float*)d_in[2];   // gate_up_proj [E, H, 2I]
    const float* w2  = (const float*)d_in[3];   // down_proj   [E, I, H]
    const int*   sel = (const int*)d_in[4];     // selected_experts [T, K]
    float* out = (float*)d_out;                 // [T, H] fp32

    cudaFuncSetAttribute(gemm1_kernel, cudaFuncAttributeMaxDynamicSharedMemorySize, SMEM_TOTAL);
    cudaFuncSetAttribute(gemm2_kernel, cudaFuncAttributeMaxDynamicSharedMemorySize, SMEM_TOTAL);

    setup_kernel<<<1, 256>>>(sel);
    gemm1_kernel<<<dim3(MAX_TILES, I_DIM / 64), 256, SMEM_TOTAL>>>(x, w1);
    gemm2_kernel<<<dim3(MAX_TILES, H_DIM / 128), 256, SMEM_TOTAL>>>(w2);
    combine_kernel<<<(T_TOK * H_DIM / 4 + 255) / 256, 256>>>(rw, out);
}

// round 6
// speedup vs baseline: 3.2346x; 1.0489x over previous
#include <cuda_runtime.h>
#include <cstdint>
#include <cmath>

// Problem constants (fixed by the dataset)
#define T_TOK 1024
#define H_DIM 2048
#define I_DIM 768
#define E_NUM 8
#define K_TOP 2
#define NROWS (T_TOK * K_TOP)      // 2048 permuted rows

#define BM 128
#define MAX_TILES 24

// ---------------- scratch (no allocations allowed) ----------------
__device__ int   g_row_src[NROWS];
__device__ int   g_pos[NROWS];
__device__ int   g_tile_expert[MAX_TILES];
__device__ int   g_tile_row[MAX_TILES];
__device__ int   g_tile_end[MAX_TILES];
__device__ int   g_num_tiles;
__device__ float g_xc[T_TOK * H_DIM];     // tf32-rounded hidden_states
__device__ float g_act[NROWS * I_DIM];    // tf32-rounded swiglu output
__device__ float g_fc2[NROWS * H_DIM];

// ---------------- PTX helpers (all sm_80-level, no 'a' features) ----------------
__device__ __forceinline__ uint32_t s2u(const void* p) {
    uint32_t a;
    asm("{ .reg .u64 t; cvta.to.shared.u64 t, %1; cvt.u32.u64 %0, t; }" : "=r"(a) : "l"(p));
    return a;
}
__device__ __forceinline__ void cp16(uint32_t dst, const void* src, uint32_t sz) {
    asm volatile("cp.async.cg.shared.global [%0], [%1], 16, %2;" :: "r"(dst), "l"(src), "r"(sz));
}
__device__ __forceinline__ void cp_commit() { asm volatile("cp.async.commit_group;" ::: "memory"); }
template<int N> __device__ __forceinline__ void cp_wait() {
    asm volatile("cp.async.wait_group %0;" :: "n"(N) : "memory");
}
__device__ __forceinline__ void ldsm4(uint32_t r[4], uint32_t addr) {
    asm volatile("ldmatrix.sync.aligned.m8n8.x4.shared.b16 {%0,%1,%2,%3}, [%4];"
        : "=r"(r[0]), "=r"(r[1]), "=r"(r[2]), "=r"(r[3]) : "r"(addr));
}
__device__ __forceinline__ uint32_t f2tf_f(float x) {
    uint32_t r;
    asm("cvt.rna.tf32.f32 %0, %1;" : "=r"(r) : "f"(x));
    return r;
}
__device__ __forceinline__ float tfr(float x) {           // tf32 round, keep as float bits
    return __uint_as_float(f2tf_f(x));
}
__device__ __forceinline__ void mma8(float* c, const uint32_t* a, uint32_t b0, uint32_t b1) {
    asm volatile(
        "mma.sync.aligned.m16n8k8.row.col.f32.tf32.tf32.f32 "
        "{%0,%1,%2,%3}, {%4,%5,%6,%7}, {%8,%9}, {%0,%1,%2,%3};"
        : "+f"(c[0]), "+f"(c[1]), "+f"(c[2]), "+f"(c[3])
        : "r"(a[0]), "r"(a[1]), "r"(a[2]), "r"(a[3]), "r"(b0), "r"(b1));
}

// SMEM layout (byte offsets into dynamic smem)
// [0,512) s_tok ; [1024 ...) two stages of {A 16KB, B 17408B (32 rows x 136 floats)}
#define STAGE_BYTES 33792
#define OFF_A(b) (1024 + (b) * STAGE_BYTES)
#define OFF_B(b) (OFF_A(b) + 16384)
#define SMEM_TOTAL 68608            // epilogue Es (128x132 f32) reuses [1024, 68608)
#define BPAD 136

// ---------------- setup ----------------
__global__ void setup_kernel(const int* __restrict__ sel) {
    __shared__ int cnt[E_NUM];
    __shared__ int run[E_NUM];
    int tid = threadIdx.x;
    if (tid < E_NUM) cnt[tid] = 0;
    __syncthreads();
    for (int i = tid; i < NROWS; i += blockDim.x)
        atomicAdd(&cnt[sel[i]], 1);
    __syncthreads();
    if (tid == 0) {
        int s = 0, nt = 0;
        for (int e = 0; e < E_NUM; e++) {
            run[e] = s;
            int c = cnt[e];
            for (int r = 0; r < c; r += BM) {
                g_tile_expert[nt] = e;
                g_tile_row[nt]    = s + r;
                g_tile_end[nt]    = s + c;
                nt++;
            }
            s += c;
        }
        g_num_tiles = nt;
    }
    __syncthreads();
    for (int i = tid; i < NROWS; i += blockDim.x) {
        int e = sel[i];
        int p = atomicAdd(&run[e], 1);
        g_row_src[p] = i;
        g_pos[i] = p;
    }
}

// ---------------- cvtx: g_xc = tf32(x) ----------------
__global__ void __launch_bounds__(256)
cvtx_kernel(const float* __restrict__ x) {
    int i = blockIdx.x * blockDim.x + threadIdx.x;
    if (i >= T_TOK * (H_DIM / 4)) return;
    float4 v = reinterpret_cast<const float4*>(x)[i];
    v.x = tfr(v.x); v.y = tfr(v.y); v.z = tfr(v.z); v.w = tfr(v.w);
    reinterpret_cast<float4*>(g_xc)[i] = v;
}

// ---------------- GEMM1: act = swiglu( Xc_gather @ W1[e] ), tf32 mma.sync ----------------
// Block: 128 rows x (gate 64 + up 64 cols of fc1).
__global__ void __launch_bounds__(256, 2)
gemm1_kernel(const float* __restrict__ w1) {
    extern __shared__ char smem[];
    uint32_t sb = s2u(smem);
    int mt = blockIdx.x;
    if (mt >= g_num_tiles) return;
    int e = g_tile_expert[mt], row0 = g_tile_row[mt], rend = g_tile_end[mt];
    int col0g = blockIdx.y * 64;

    int tid = threadIdx.x, lane = tid & 31, wid = tid >> 5;
    int warpM = wid >> 2, warpN = wid & 3;
    int gid = lane >> 2, tig = lane & 3;

    int* s_tok = (int*)smem;
    if (tid < 128) {
        int r = row0 + tid;
        s_tok[tid] = (r < rend) ? (g_row_src[r] / K_TOP) : -1;
    }
    __syncthreads();

    const float* W = w1 + (size_t)e * H_DIM * (2 * I_DIM);
    int am = tid >> 1;
    int tokm = s_tok[am];
    const float* asrc = g_xc + (size_t)(tokm < 0 ? 0 : tokm) * H_DIM;
    uint32_t asz = (tokm < 0) ? 0u : 16u;
    int ac0 = (tid & 1) * 4;
    int akey = am & 7;

    auto load_chunk = [&](int ci, int buf) {
        int k0 = ci * 32;
        uint32_t Ab = sb + OFF_A(buf);
        #pragma unroll
        for (int c = 0; c < 4; c++) {
            int cc = ac0 + c;
            cp16(Ab + am * 128 + ((cc ^ akey) << 4), asrc + k0 + cc * 4, asz);
        }
        uint32_t Bb = sb + OFF_B(buf);
        #pragma unroll
        for (int it = 0; it < 4; it++) {
            int q = tid + it * 256;
            int k = q >> 5, c16 = q & 31, n = c16 * 4;
            const float* src = (n < 64)
                ? W + (size_t)(k0 + k) * (2 * I_DIM) + col0g + n
                : W + (size_t)(k0 + k) * (2 * I_DIM) + I_DIM + col0g + (n - 64);
            cp16(Bb + k * (BPAD * 4) + n * 4, src, 16);
        }
        cp_commit();
    };

    int mlane = lane & 15, extra = lane >> 4, key = lane & 7;
    int boff = tig * BPAD + warpN * 32 + gid;

    float acc[4][4][4] = {};
    const int NC = H_DIM / 32;   // 64
    load_chunk(0, 0);
    for (int i = 0; i < NC; i++) {
        int b = i & 1;
        if (i + 1 < NC) { load_chunk(i + 1, b ^ 1); cp_wait<1>(); }
        else           { cp_wait<0>(); }
        __syncthreads();

        uint32_t Ab = sb + OFF_A(b);
        const float* Bsp = (const float*)(smem + OFF_B(b));
        #pragma unroll
        for (int ks = 0; ks < 4; ks++) {
            uint32_t a[4][4];
            #pragma unroll
            for (int mi = 0; mi < 4; mi++) {
                uint32_t addr = Ab + (uint32_t)((warpM * 64 + mi * 16 + mlane) * 128
                              + ((((ks << 1) | extra) ^ key) << 4));
                ldsm4(a[mi], addr);
            }
            #pragma unroll
            for (int j = 0; j < 4; j++) {
                uint32_t b0 = f2tf_f(Bsp[boff + ks * (8 * BPAD) + j * 8]);
                uint32_t b1 = f2tf_f(Bsp[boff + ks * (8 * BPAD) + j * 8 + 4 * BPAD]);
                #pragma unroll
                for (int mi = 0; mi < 4; mi++)
                    mma8(acc[mi][j], a[mi], b0, b1);
            }
        }
        __syncthreads();
    }

    // epilogue: frags -> smem, then swiglu (tf32-rounded) -> g_act
    float* Es = (float*)(smem + 1024);
    #pragma unroll
    for (int mi = 0; mi < 4; mi++)
        #pragma unroll
        for (int j = 0; j < 4; j++) {
            int row = warpM * 64 + mi * 16 + gid;
            int col = warpN * 32 + j * 8 + 2 * tig;
            *(float2*)&Es[row * 132 + col]       = make_float2(acc[mi][j][0], acc[mi][j][1]);
            *(float2*)&Es[(row + 8) * 132 + col] = make_float2(acc[mi][j][2], acc[mi][j][3]);
        }
    __syncthreads();

    int rr = tid >> 1;
    int r  = row0 + rr;
    int cb = (tid & 1) * 32;
    if (r < rend) {
        float* dst = g_act + (size_t)r * I_DIM + col0g + cb;
        #pragma unroll
        for (int jj = 0; jj < 32; jj += 4) {
            float4 gv = *(float4*)&Es[rr * 132 + cb + jj];
            float4 uv = *(float4*)&Es[rr * 132 + 64 + cb + jj];
            float4 o;
            o.x = tfr(gv.x * (1.0f / (1.0f + __expf(-gv.x))) * uv.x);
            o.y = tfr(gv.y * (1.0f / (1.0f + __expf(-gv.y))) * uv.y);
            o.z = tfr(gv.z * (1.0f / (1.0f + __expf(-gv.z))) * uv.z);
            o.w = tfr(gv.w * (1.0f / (1.0f + __expf(-gv.w))) * uv.w);
            *(float4*)(dst + jj) = o;
        }
    }
}

// ---------------- GEMM2: fc2 = act @ W2[e], tf32 mma.sync ----------------
// Block: 128 rows x 128 cols.
__global__ void __launch_bounds__(256, 2)
gemm2_kernel(const float* __restrict__ w2) {
    extern __shared__ char smem[];
    uint32_t sb = s2u(smem);
    int mt = blockIdx.x;
    if (mt >= g_num_tiles) return;
    int e = g_tile_expert[mt], row0 = g_tile_row[mt], rend = g_tile_end[mt];
    int col0 = blockIdx.y * 128;

    int tid = threadIdx.x, lane = tid & 31, wid = tid >> 5;
    int warpM = wid >> 2, warpN = wid & 3;
    int gid = lane >> 2, tig = lane & 3;

    const float* W = w2 + (size_t)e * I_DIM * H_DIM;
    int am = tid >> 1;
    int rrow = row0 + am; if (rrow >= NROWS) rrow = NROWS - 1;   // clamp; masked later
    const float* asrc = g_act + (size_t)rrow * I_DIM;
    int ac0 = (tid & 1) * 4;
    int akey = am & 7;

    auto load_chunk = [&](int ci, int buf) {
        int k0 = ci * 32;
        uint32_t Ab = sb + OFF_A(buf);
        #pragma unroll
        for (int c = 0; c < 4; c++) {
            int cc = ac0 + c;
            cp16(Ab + am * 128 + ((cc ^ akey) << 4), asrc + k0 + cc * 4, 16);
        }
        uint32_t Bb = sb + OFF_B(buf);
        #pragma unroll
        for (int it = 0; it < 4; it++) {
            int q = tid + it * 256;
            int k = q >> 5, c16 = q & 31, n = c16 * 4;
            cp16(Bb + k * (BPAD * 4) + n * 4, W + (size_t)(k0 + k) * H_DIM + col0 + n, 16);
        }
        cp_commit();
    };

    int mlane = lane & 15, extra = lane >> 4, key = lane & 7;
    int boff = tig * BPAD + warpN * 32 + gid;

    float acc[4][4][4] = {};
    const int NC = I_DIM / 32;   // 24
    load_chunk(0, 0);
    for (int i = 0; i < NC; i++) {
        int b = i & 1;
        if (i + 1 < NC) { load_chunk(i + 1, b ^ 1); cp_wait<1>(); }
        else           { cp_wait<0>(); }
        __syncthreads();

        uint32_t Ab = sb + OFF_A(b);
        const float* Bsp = (const float*)(smem + OFF_B(b));
        #pragma unroll
        for (int ks = 0; ks < 4; ks++) {
            uint32_t a[4][4];
            #pragma unroll
            for (int mi = 0; mi < 4; mi++) {
                uint32_t addr = Ab + (uint32_t)((warpM * 64 + mi * 16 + mlane) * 128
                              + ((((ks << 1) | extra) ^ key) << 4));
                ldsm4(a[mi], addr);
            }
            #pragma unroll
            for (int j = 0; j < 4; j++) {
                uint32_t b0 = f2tf_f(Bsp[boff + ks * (8 * BPAD) + j * 8]);
                uint32_t b1 = f2tf_f(Bsp[boff + ks * (8 * BPAD) + j * 8 + 4 * BPAD]);
                #pragma unroll
                for (int mi = 0; mi < 4; mi++)
                    mma8(acc[mi][j], a[mi], b0, b1);
            }
        }
        __syncthreads();
    }

    // epilogue: direct to g_fc2
    #pragma unroll
    for (int mi = 0; mi < 4; mi++) {
        int row = row0 + warpM * 64 + mi * 16 + gid;
        #pragma unroll
        for (int j = 0; j < 4; j++) {
            int col = col0 + warpN * 32 + j * 8 + 2 * tig;
            if (row < rend)
                *(float2*)&g_fc2[(size_t)row * H_DIM + col] =
                    make_float2(acc[mi][j][0], acc[mi][j][1]);
            if (row + 8 < rend)
                *(float2*)&g_fc2[(size_t)(row + 8) * H_DIM + col] =
                    make_float2(acc[mi][j][2], acc[mi][j][3]);
        }
    }
}

// ---------------- combine ----------------
__global__ void __launch_bounds__(256)
combine_kernel(const float* __restrict__ rw, float* __restrict__ out) {
    int i = blockIdx.x * blockDim.x + threadIdx.x;
    if (i >= T_TOK * (H_DIM / 4)) return;
    int t  = i >> 9;
    int h4 = i & 511;
    int p0 = g_pos[2 * t];
    int p1 = g_pos[2 * t + 1];
    float w0 = rw[2 * t];
    float w1 = rw[2 * t + 1];
    float4 v0 = *reinterpret_cast<const float4*>(&g_fc2[(size_t)p0 * H_DIM + h4 * 4]);
    float4 v1 = *reinterpret_cast<const float4*>(&g_fc2[(size_t)p1 * H_DIM + h4 * 4]);
    float4 o;
    o.x = w0 * v0.x + w1 * v1.x;
    o.y = w0 * v0.y + w1 * v1.y;
    o.z = w0 * v0.z + w1 * v1.z;
    o.w = w0 * v0.w + w1 * v1.w;
    reinterpret_cast<float4*>(out)[i] = o;
}

// ---------------- launch ----------------
extern "C" void kernel_launch(void* const* d_in, const int* in_sizes, int n_in,
                              void* d_out, int out_size) {
    const float* x   = (const float*)d_in[0];   // hidden_states [T, H]
    const float* rw  = (const float*)d_in[1];   // routing_weights [T, K]
    const float* w1  = (const float*)d_in[2];   // gate_up_proj [E, H, 2I]
    const float* w2  = (const float*)d_in[3];   // down_proj   [E, I, H]
    const int*   sel = (const int*)d_in[4];     // selected_experts [T, K]
    float* out = (float*)d_out;                 // [T, H] fp32

    cudaFuncSetAttribute(gemm1_kernel, cudaFuncAttributeMaxDynamicSharedMemorySize, SMEM_TOTAL);
    cudaFuncSetAttribute(gemm2_kernel, cudaFuncAttributeMaxDynamicSharedMemorySize, SMEM_TOTAL);

    setup_kernel<<<1, 256>>>(sel);
    cvtx_kernel<<<(T_TOK * H_DIM / 4 + 255) / 256, 256>>>(x);
    gemm1_kernel<<<dim3(MAX_TILES, I_DIM / 64), 256, SMEM_TOTAL>>>(w1);
    gemm2_kernel<<<dim3(MAX_TILES, H_DIM / 128), 256, SMEM_TOTAL>>>(w2);
    combine_kernel<<<(T_TOK * H_DIM / 4 + 255) / 256, 256>>>(rw, out);
}

// round 7
// speedup vs baseline: 3.3287x; 1.0291x over previous
#include <cuda_runtime.h>
#include <cstdint>
#include <cmath>

// Problem constants (fixed by the dataset)
#define T_TOK 1024
#define H_DIM 2048
#define I_DIM 768
#define E_NUM 8
#define K_TOP 2
#define NROWS (T_TOK * K_TOP)      // 2048 permuted rows

#define BM 128
#define MAX_TILES 24

// ---------------- scratch (no allocations allowed) ----------------
__device__ int   g_row_src[NROWS];
__device__ int   g_pos[NROWS];
__device__ int   g_tile_expert[MAX_TILES];
__device__ int   g_tile_row[MAX_TILES];
__device__ int   g_tile_end[MAX_TILES];
__device__ int   g_num_tiles;
__device__ float g_xc[T_TOK * H_DIM];     // tf32-rounded hidden_states
__device__ float g_act[NROWS * I_DIM];    // tf32-rounded swiglu output
__device__ float g_fc2[NROWS * H_DIM];

// ---------------- PTX helpers (all sm_80-level, no 'a' features) ----------------
__device__ __forceinline__ uint32_t s2u(const void* p) {
    uint32_t a;
    asm("{ .reg .u64 t; cvta.to.shared.u64 t, %1; cvt.u32.u64 %0, t; }" : "=r"(a) : "l"(p));
    return a;
}
__device__ __forceinline__ void cp16(uint32_t dst, const void* src, uint32_t sz) {
    asm volatile("cp.async.cg.shared.global [%0], [%1], 16, %2;" :: "r"(dst), "l"(src), "r"(sz));
}
__device__ __forceinline__ void cp_commit() { asm volatile("cp.async.commit_group;" ::: "memory"); }
template<int N> __device__ __forceinline__ void cp_wait() {
    asm volatile("cp.async.wait_group %0;" :: "n"(N) : "memory");
}
__device__ __forceinline__ void ldsm4(uint32_t r[4], uint32_t addr) {
    asm volatile("ldmatrix.sync.aligned.m8n8.x4.shared.b16 {%0,%1,%2,%3}, [%4];"
        : "=r"(r[0]), "=r"(r[1]), "=r"(r[2]), "=r"(r[3]) : "r"(addr));
}
__device__ __forceinline__ uint32_t f2tf_f(float x) {
    uint32_t r;
    asm("cvt.rna.tf32.f32 %0, %1;" : "=r"(r) : "f"(x));
    return r;
}
__device__ __forceinline__ float tfr(float x) {           // tf32 round, keep as float bits
    return __uint_as_float(f2tf_f(x));
}
__device__ __forceinline__ void mma8(float* c, const uint32_t* a, uint32_t b0, uint32_t b1) {
    asm volatile(
        "mma.sync.aligned.m16n8k8.row.col.f32.tf32.tf32.f32 "
        "{%0,%1,%2,%3}, {%4,%5,%6,%7}, {%8,%9}, {%0,%1,%2,%3};"
        : "+f"(c[0]), "+f"(c[1]), "+f"(c[2]), "+f"(c[3])
        : "r"(a[0]), "r"(a[1]), "r"(a[2]), "r"(a[3]), "r"(b0), "r"(b1));
}

// SMEM layout (byte offsets into dynamic smem)
// [0,512) s_tok ; [1024 ...) THREE stages of {A 16KB, B 17408B (32 rows x 136 floats)}
#define STAGE_BYTES 33792
#define OFF_A(b) (1024 + (b) * STAGE_BYTES)
#define OFF_B(b) (OFF_A(b) + 16384)
#define SMEM_TOTAL 102400           // 1024 + 3*33792; epilogue Es (128x132 f32) reuses it
#define BPAD 136

// ---------------- setup ----------------
__global__ void setup_kernel(const int* __restrict__ sel) {
    __shared__ int cnt[E_NUM];
    __shared__ int run[E_NUM];
    int tid = threadIdx.x;
    if (tid < E_NUM) cnt[tid] = 0;
    __syncthreads();
    for (int i = tid; i < NROWS; i += blockDim.x)
        atomicAdd(&cnt[sel[i]], 1);
    __syncthreads();
    if (tid == 0) {
        int s = 0, nt = 0;
        for (int e = 0; e < E_NUM; e++) {
            run[e] = s;
            int c = cnt[e];
            for (int r = 0; r < c; r += BM) {
                g_tile_expert[nt] = e;
                g_tile_row[nt]    = s + r;
                g_tile_end[nt]    = s + c;
                nt++;
            }
            s += c;
        }
        g_num_tiles = nt;
    }
    __syncthreads();
    for (int i = tid; i < NROWS; i += blockDim.x) {
        int e = sel[i];
        int p = atomicAdd(&run[e], 1);
        g_row_src[p] = i;
        g_pos[i] = p;
    }
}

// ---------------- cvtx: g_xc = tf32(x) ----------------
__global__ void __launch_bounds__(256)
cvtx_kernel(const float* __restrict__ x) {
    int i = blockIdx.x * blockDim.x + threadIdx.x;
    if (i >= T_TOK * (H_DIM / 4)) return;
    float4 v = reinterpret_cast<const float4*>(x)[i];
    v.x = tfr(v.x); v.y = tfr(v.y); v.z = tfr(v.z); v.w = tfr(v.w);
    reinterpret_cast<float4*>(g_xc)[i] = v;
}

// ---------------- GEMM1: act = swiglu( Xc_gather @ W1[e] ), tf32 mma.sync ----------------
// Block: 128 rows x (gate 64 + up 64 cols of fc1). 3-stage cp.async pipeline.
__global__ void __launch_bounds__(256, 2)
gemm1_kernel(const float* __restrict__ w1) {
    extern __shared__ char smem[];
    uint32_t sb = s2u(smem);
    int mt = blockIdx.x;
    if (mt >= g_num_tiles) return;
    int e = g_tile_expert[mt], row0 = g_tile_row[mt], rend = g_tile_end[mt];
    int col0g = blockIdx.y * 64;

    int tid = threadIdx.x, lane = tid & 31, wid = tid >> 5;
    int warpM = wid >> 2, warpN = wid & 3;
    int gid = lane >> 2, tig = lane & 3;

    int* s_tok = (int*)smem;
    if (tid < 128) {
        int r = row0 + tid;
        s_tok[tid] = (r < rend) ? (g_row_src[r] / K_TOP) : -1;
    }
    __syncthreads();

    const float* W = w1 + (size_t)e * H_DIM * (2 * I_DIM);
    int am = tid >> 1;
    int tokm = s_tok[am];
    const float* asrc = g_xc + (size_t)(tokm < 0 ? 0 : tokm) * H_DIM;
    uint32_t asz = (tokm < 0) ? 0u : 16u;
    int ac0 = (tid & 1) * 4;
    int akey = am & 7;

    auto load_chunk = [&](int ci, int buf) {
        int k0 = ci * 32;
        uint32_t Ab = sb + OFF_A(buf);
        #pragma unroll
        for (int c = 0; c < 4; c++) {
            int cc = ac0 + c;
            cp16(Ab + am * 128 + ((cc ^ akey) << 4), asrc + k0 + cc * 4, asz);
        }
        uint32_t Bb = sb + OFF_B(buf);
        #pragma unroll
        for (int it = 0; it < 4; it++) {
            int q = tid + it * 256;
            int k = q >> 5, c16 = q & 31, n = c16 * 4;
            const float* src = (n < 64)
                ? W + (size_t)(k0 + k) * (2 * I_DIM) + col0g + n
                : W + (size_t)(k0 + k) * (2 * I_DIM) + I_DIM + col0g + (n - 64);
            cp16(Bb + k * (BPAD * 4) + n * 4, src, 16);
        }
        cp_commit();
    };

    int mlane = lane & 15, extra = lane >> 4, key = lane & 7;
    int boff = tig * BPAD + warpN * 32 + gid;

    float acc[4][4][4] = {};
    const int NC = H_DIM / 32;   // 64
    load_chunk(0, 0);
    load_chunk(1, 1);
    int bc = 0;
    for (int i = 0; i < NC; i++) {
        cp_wait<1>();            // chunk i resident
        __syncthreads();         // also proves all warps finished compute(i-1)
        int bn = bc + 2; if (bn >= 3) bn -= 3;
        if (i + 2 < NC) load_chunk(i + 2, bn);
        else            cp_commit();            // keep group counting uniform

        uint32_t Ab = sb + OFF_A(bc);
        const float* Bsp = (const float*)(smem + OFF_B(bc));
        #pragma unroll
        for (int ks = 0; ks < 4; ks++) {
            uint32_t a[4][4];
            #pragma unroll
            for (int mi = 0; mi < 4; mi++) {
                uint32_t addr = Ab + (uint32_t)((warpM * 64 + mi * 16 + mlane) * 128
                              + ((((ks << 1) | extra) ^ key) << 4));
                ldsm4(a[mi], addr);
            }
            #pragma unroll
            for (int j = 0; j < 4; j++) {
                uint32_t b0 = f2tf_f(Bsp[boff + ks * (8 * BPAD) + j * 8]);
                uint32_t b1 = f2tf_f(Bsp[boff + ks * (8 * BPAD) + j * 8 + 4 * BPAD]);
                #pragma unroll
                for (int mi = 0; mi < 4; mi++)
                    mma8(acc[mi][j], a[mi], b0, b1);
            }
        }
        bc = (bc + 1 == 3) ? 0 : bc + 1;
    }

    // epilogue: frags -> smem, then swiglu (tf32-rounded) -> g_act
    __syncthreads();             // Es overlaps the pipeline buffers
    float* Es = (float*)(smem + 1024);
    #pragma unroll
    for (int mi = 0; mi < 4; mi++)
        #pragma unroll
        for (int j = 0; j < 4; j++) {
            int row = warpM * 64 + mi * 16 + gid;
            int col = warpN * 32 + j * 8 + 2 * tig;
            *(float2*)&Es[row * 132 + col]       = make_float2(acc[mi][j][0], acc[mi][j][1]);
            *(float2*)&Es[(row + 8) * 132 + col] = make_float2(acc[mi][j][2], acc[mi][j][3]);
        }
    __syncthreads();

    int rr = tid >> 1;
    int r  = row0 + rr;
    int cb = (tid & 1) * 32;
    if (r < rend) {
        float* dst = g_act + (size_t)r * I_DIM + col0g + cb;
        #pragma unroll
        for (int jj = 0; jj < 32; jj += 4) {
            float4 gv = *(float4*)&Es[rr * 132 + cb + jj];
            float4 uv = *(float4*)&Es[rr * 132 + 64 + cb + jj];
            float4 o;
            o.x = tfr(gv.x * (1.0f / (1.0f + __expf(-gv.x))) * uv.x);
            o.y = tfr(gv.y * (1.0f / (1.0f + __expf(-gv.y))) * uv.y);
            o.z = tfr(gv.z * (1.0f / (1.0f + __expf(-gv.z))) * uv.z);
            o.w = tfr(gv.w * (1.0f / (1.0f + __expf(-gv.w))) * uv.w);
            *(float4*)(dst + jj) = o;
        }
    }
}

// ---------------- GEMM2: fc2 = act @ W2[e], tf32 mma.sync ----------------
// Block: 128 rows x 128 cols. 3-stage cp.async pipeline.
__global__ void __launch_bounds__(256, 2)
gemm2_kernel(const float* __restrict__ w2) {
    extern __shared__ char smem[];
    uint32_t sb = s2u(smem);
    int mt = blockIdx.x;
    if (mt >= g_num_tiles) return;
    int e = g_tile_expert[mt], row0 = g_tile_row[mt], rend = g_tile_end[mt];
    int col0 = blockIdx.y * 128;

    int tid = threadIdx.x, lane = tid & 31, wid = tid >> 5;
    int warpM = wid >> 2, warpN = wid & 3;
    int gid = lane >> 2, tig = lane & 3;

    const float* W = w2 + (size_t)e * I_DIM * H_DIM;
    int am = tid >> 1;
    int rrow = row0 + am; if (rrow >= NROWS) rrow = NROWS - 1;   // clamp; masked later
    const float* asrc = g_act + (size_t)rrow * I_DIM;
    int ac0 = (tid & 1) * 4;
    int akey = am & 7;

    auto load_chunk = [&](int ci, int buf) {
        int k0 = ci * 32;
        uint32_t Ab = sb + OFF_A(buf);
        #pragma unroll
        for (int c = 0; c < 4; c++) {
            int cc = ac0 + c;
            cp16(Ab + am * 128 + ((cc ^ akey) << 4), asrc + k0 + cc * 4, 16);
        }
        uint32_t Bb = sb + OFF_B(buf);
        #pragma unroll
        for (int it = 0; it < 4; it++) {
            int q = tid + it * 256;
            int k = q >> 5, c16 = q & 31, n = c16 * 4;
            cp16(Bb + k * (BPAD * 4) + n * 4, W + (size_t)(k0 + k) * H_DIM + col0 + n, 16);
        }
        cp_commit();
    };

    int mlane = lane & 15, extra = lane >> 4, key = lane & 7;
    int boff = tig * BPAD + warpN * 32 + gid;

    float acc[4][4][4] = {};
    const int NC = I_DIM / 32;   // 24
    load_chunk(0, 0);
    load_chunk(1, 1);
    int bc = 0;
    for (int i = 0; i < NC; i++) {
        cp_wait<1>();
        __syncthreads();
        int bn = bc + 2; if (bn >= 3) bn -= 3;
        if (i + 2 < NC) load_chunk(i + 2, bn);
        else            cp_commit();

        uint32_t Ab = sb + OFF_A(bc);
        const float* Bsp = (const float*)(smem + OFF_B(bc));
        #pragma unroll
        for (int ks = 0; ks < 4; ks++) {
            uint32_t a[4][4];
            #pragma unroll
            for (int mi = 0; mi < 4; mi++) {
                uint32_t addr = Ab + (uint32_t)((warpM * 64 + mi * 16 + mlane) * 128
                              + ((((ks << 1) | extra) ^ key) << 4));
                ldsm4(a[mi], addr);
            }
            #pragma unroll
            for (int j = 0; j < 4; j++) {
                uint32_t b0 = f2tf_f(Bsp[boff + ks * (8 * BPAD) + j * 8]);
                uint32_t b1 = f2tf_f(Bsp[boff + ks * (8 * BPAD) + j * 8 + 4 * BPAD]);
                #pragma unroll
                for (int mi = 0; mi < 4; mi++)
                    mma8(acc[mi][j], a[mi], b0, b1);
            }
        }
        bc = (bc + 1 == 3) ? 0 : bc + 1;
    }

    // epilogue: direct to g_fc2
    #pragma unroll
    for (int mi = 0; mi < 4; mi++) {
        int row = row0 + warpM * 64 + mi * 16 + gid;
        #pragma unroll
        for (int j = 0; j < 4; j++) {
            int col = col0 + warpN * 32 + j * 8 + 2 * tig;
            if (row < rend)
                *(float2*)&g_fc2[(size_t)row * H_DIM + col] =
                    make_float2(acc[mi][j][0], acc[mi][j][1]);
            if (row + 8 < rend)
                *(float2*)&g_fc2[(size_t)(row + 8) * H_DIM + col] =
                    make_float2(acc[mi][j][2], acc[mi][j][3]);
        }
    }
}

// ---------------- combine ----------------
__global__ void __launch_bounds__(256)
combine_kernel(const float* __restrict__ rw, float* __restrict__ out) {
    int i = blockIdx.x * blockDim.x + threadIdx.x;
    if (i >= T_TOK * (H_DIM / 4)) return;
    int t  = i >> 9;
    int h4 = i & 511;
    int p0 = g_pos[2 * t];
    int p1 = g_pos[2 * t + 1];
    float w0 = rw[2 * t];
    float w1 = rw[2 * t + 1];
    float4 v0 = *reinterpret_cast<const float4*>(&g_fc2[(size_t)p0 * H_DIM + h4 * 4]);
    float4 v1 = *reinterpret_cast<const float4*>(&g_fc2[(size_t)p1 * H_DIM + h4 * 4]);
    float4 o;
    o.x = w0 * v0.x + w1 * v1.x;
    o.y = w0 * v0.y + w1 * v1.y;
    o.z = w0 * v0.z + w1 * v1.z;
    o.w = w0 * v0.w + w1 * v1.w;
    reinterpret_cast<float4*>(out)[i] = o;
}

// ---------------- launch ----------------
extern "C" void kernel_launch(void* const* d_in, const int* in_sizes, int n_in,
                              void* d_out, int out_size) {
    const float* x   = (const float*)d_in[0];   // hidden_states [T, H]
    const float* rw  = (const float*)d_in[1];   // routing_weights [T, K]
    const float* w1  = (const float*)d_in[2];   // gate_up_proj [E, H, 2I]
    const float* w2  = (const float*)d_in[3];   // down_proj   [E, I, H]
    const int*   sel = (const int*)d_in[4];     // selected_experts [T, K]
    float* out = (float*)d_out;                 // [T, H] fp32

    cudaFuncSetAttribute(gemm1_kernel, cudaFuncAttributeMaxDynamicSharedMemorySize, SMEM_TOTAL);
    cudaFuncSetAttribute(gemm2_kernel, cudaFuncAttributeMaxDynamicSharedMemorySize, SMEM_TOTAL);

    setup_kernel<<<1, 256>>>(sel);
    cvtx_kernel<<<(T_TOK * H_DIM / 4 + 255) / 256, 256>>>(x);
    gemm1_kernel<<<dim3(MAX_TILES, I_DIM / 64), 256, SMEM_TOTAL>>>(w1);
    gemm2_kernel<<<dim3(MAX_TILES, H_DIM / 128), 256, SMEM_TOTAL>>>(w2);
    combine_kernel<<<(T_TOK * H_DIM / 4 + 255) / 256, 256>>>(rw, out);
}

// round 8
// speedup vs baseline: 3.4925x; 1.0492x over previous
#include <cuda_runtime.h>
#include <cstdint>
#include <cmath>

// Problem constants (fixed by the dataset)
#define T_TOK 1024
#define H_DIM 2048
#define I_DIM 768
#define E_NUM 8
#define K_TOP 2
#define NROWS (T_TOK * K_TOP)      // 2048 permuted rows

#define BM 64
#define MAX_TILES 40               // sum_e ceil(cnt_e/64) <= 32 + 7 = 39

// ---------------- scratch (no allocations allowed) ----------------
__device__ int   g_row_src[NROWS];
__device__ int   g_pos[NROWS];
__device__ int   g_tile_expert[MAX_TILES];
__device__ int   g_tile_row[MAX_TILES];
__device__ int   g_tile_end[MAX_TILES];
__device__ int   g_num_tiles;
__device__ float g_xc[T_TOK * H_DIM];     // tf32-rounded hidden_states
__device__ float g_act[NROWS * I_DIM];    // tf32-rounded swiglu output
__device__ float g_fc2[NROWS * H_DIM];

// ---------------- PTX helpers (all sm_80-level, no 'a' features) ----------------
__device__ __forceinline__ uint32_t s2u(const void* p) {
    uint32_t a;
    asm("{ .reg .u64 t; cvta.to.shared.u64 t, %1; cvt.u32.u64 %0, t; }" : "=r"(a) : "l"(p));
    return a;
}
__device__ __forceinline__ void cp16(uint32_t dst, const void* src, uint32_t sz) {
    asm volatile("cp.async.cg.shared.global [%0], [%1], 16, %2;" :: "r"(dst), "l"(src), "r"(sz));
}
__device__ __forceinline__ void cp_commit() { asm volatile("cp.async.commit_group;" ::: "memory"); }
template<int N> __device__ __forceinline__ void cp_wait() {
    asm volatile("cp.async.wait_group %0;" :: "n"(N) : "memory");
}
__device__ __forceinline__ void ldsm4(uint32_t r[4], uint32_t addr) {
    asm volatile("ldmatrix.sync.aligned.m8n8.x4.shared.b16 {%0,%1,%2,%3}, [%4];"
        : "=r"(r[0]), "=r"(r[1]), "=r"(r[2]), "=r"(r[3]) : "r"(addr));
}
__device__ __forceinline__ uint32_t f2tf_f(float x) {
    uint32_t r;
    asm("cvt.rna.tf32.f32 %0, %1;" : "=r"(r) : "f"(x));
    return r;
}
__device__ __forceinline__ float tfr(float x) {           // tf32 round, keep as float bits
    return __uint_as_float(f2tf_f(x));
}
__device__ __forceinline__ void mma8(float* c, const uint32_t* a, uint32_t b0, uint32_t b1) {
    asm volatile(
        "mma.sync.aligned.m16n8k8.row.col.f32.tf32.tf32.f32 "
        "{%0,%1,%2,%3}, {%4,%5,%6,%7}, {%8,%9}, {%0,%1,%2,%3};"
        : "+f"(c[0]), "+f"(c[1]), "+f"(c[2]), "+f"(c[3])
        : "r"(a[0]), "r"(a[1]), "r"(a[2]), "r"(a[3]), "r"(b0), "r"(b1));
}

// SMEM layout: THREE stages of {A 8KB (64 rows x 32 f), B 16896B (32 rows x 132 f)}
#define BPAD 132
#define STAGE_BYTES 25088
#define OFF_A(b) ((b) * STAGE_BYTES)
#define OFF_B(b) (OFF_A(b) + 8192)
#define SMEM_TOTAL 75264            // 3 stages; gemm1 epilogue Es (64x132 f32) reuses it

// ---------------- setup ----------------
__global__ void setup_kernel(const int* __restrict__ sel) {
    __shared__ int cnt[E_NUM];
    __shared__ int run[E_NUM];
    int tid = threadIdx.x;
    if (tid < E_NUM) cnt[tid] = 0;
    __syncthreads();
    for (int i = tid; i < NROWS; i += blockDim.x)
        atomicAdd(&cnt[sel[i]], 1);
    __syncthreads();
    if (tid == 0) {
        int s = 0, nt = 0;
        for (int e = 0; e < E_NUM; e++) {
            run[e] = s;
            int c = cnt[e];
            for (int r = 0; r < c; r += BM) {
                g_tile_expert[nt] = e;
                g_tile_row[nt]    = s + r;
                g_tile_end[nt]    = s + c;
                nt++;
            }
            s += c;
        }
        g_num_tiles = nt;
    }
    __syncthreads();
    for (int i = tid; i < NROWS; i += blockDim.x) {
        int e = sel[i];
        int p = atomicAdd(&run[e], 1);
        g_row_src[p] = i;
        g_pos[i] = p;
    }
}

// ---------------- cvtx: g_xc = tf32(x) ----------------
__global__ void __launch_bounds__(256)
cvtx_kernel(const float* __restrict__ x) {
    int i = blockIdx.x * blockDim.x + threadIdx.x;
    if (i >= T_TOK * (H_DIM / 4)) return;
    float4 v = reinterpret_cast<const float4*>(x)[i];
    v.x = tfr(v.x); v.y = tfr(v.y); v.z = tfr(v.z); v.w = tfr(v.w);
    reinterpret_cast<float4*>(g_xc)[i] = v;
}

// ---------------- GEMM1: act = swiglu( Xc_gather @ W1[e] ), tf32 mma.sync ----------------
// Block: 64 rows x (gate 64 + up 64 cols). Warps 2x4, warp tile 32x32.
__global__ void __launch_bounds__(256, 3)
gemm1_kernel(const float* __restrict__ w1) {
    extern __shared__ char smem[];
    uint32_t sb = s2u(smem);
    int mt = blockIdx.x;
    if (mt >= g_num_tiles) return;
    int e = g_tile_expert[mt], row0 = g_tile_row[mt], rend = g_tile_end[mt];
    int col0g = blockIdx.y * 64;

    int tid = threadIdx.x, lane = tid & 31, wid = tid >> 5;
    int warpM = wid >> 2, warpN = wid & 3;
    int gid = lane >> 2, tig = lane & 3;

    const float* W = w1 + (size_t)e * H_DIM * (2 * I_DIM);
    // A loader: row am (0..63), 2 cp16 at 16B-units ac0, ac0+1 (XOR-swizzled)
    int am = tid >> 2;
    int ac0 = (tid & 3) * 2;
    int akey = am & 7;
    int arow = row0 + am;
    int tokm = (arow < rend) ? (g_row_src[arow] / K_TOP) : -1;
    const float* asrc = g_xc + (size_t)(tokm < 0 ? 0 : tokm) * H_DIM;
    uint32_t asz = (tokm < 0) ? 0u : 16u;

    auto load_chunk = [&](int ci, int buf) {
        int k0 = ci * 32;
        uint32_t Ab = sb + OFF_A(buf);
        cp16(Ab + am * 128 + ((ac0 ^ akey) << 4),       asrc + k0 + ac0 * 4, asz);
        cp16(Ab + am * 128 + (((ac0 + 1) ^ akey) << 4), asrc + k0 + ac0 * 4 + 4, asz);
        uint32_t Bb = sb + OFF_B(buf);
        #pragma unroll
        for (int it = 0; it < 4; it++) {
            int q = tid + it * 256;
            int k = q >> 5, c16 = q & 31, n = c16 * 4;
            const float* src = (n < 64)
                ? W + (size_t)(k0 + k) * (2 * I_DIM) + col0g + n
                : W + (size_t)(k0 + k) * (2 * I_DIM) + I_DIM + col0g + (n - 64);
            cp16(Bb + k * (BPAD * 4) + n * 4, src, 16);
        }
        cp_commit();
    };

    int mlane = lane & 15, extra = lane >> 4, key = lane & 7;
    int boff = tig * BPAD + warpN * 32 + gid;

    float acc[2][4][4] = {};
    const int NC = H_DIM / 32;   // 64
    load_chunk(0, 0);
    load_chunk(1, 1);
    int bc = 0;
    for (int i = 0; i < NC; i++) {
        cp_wait<1>();            // chunk i resident (this thread)
        __syncthreads();         // all threads' chunk-i copies visible; compute(i-1) done
        int bn = bc + 2; if (bn >= 3) bn -= 3;
        if (i + 2 < NC) load_chunk(i + 2, bn);
        else            cp_commit();            // keep group counting uniform

        uint32_t Ab = sb + OFF_A(bc);
        const float* Bsp = (const float*)(smem + OFF_B(bc));
        #pragma unroll
        for (int ks = 0; ks < 4; ks++) {
            uint32_t a[2][4];
            #pragma unroll
            for (int mi = 0; mi < 2; mi++) {
                uint32_t addr = Ab + (uint32_t)((warpM * 32 + mi * 16 + mlane) * 128
                              + ((((ks << 1) | extra) ^ key) << 4));
                ldsm4(a[mi], addr);
            }
            #pragma unroll
            for (int j = 0; j < 4; j++) {
                uint32_t b0 = f2tf_f(Bsp[boff + ks * (8 * BPAD) + j * 8]);
                uint32_t b1 = f2tf_f(Bsp[boff + ks * (8 * BPAD) + j * 8 + 4 * BPAD]);
                mma8(acc[0][j], a[0], b0, b1);
                mma8(acc[1][j], a[1], b0, b1);
            }
        }
        bc = (bc + 1 == 3) ? 0 : bc + 1;
    }

    // epilogue: frags -> smem, then swiglu (tf32-rounded) -> g_act
    __syncthreads();             // Es overlaps the pipeline buffers
    float* Es = (float*)smem;
    #pragma unroll
    for (int mi = 0; mi < 2; mi++)
        #pragma unroll
        for (int j = 0; j < 4; j++) {
            int row = warpM * 32 + mi * 16 + gid;
            int col = warpN * 32 + j * 8 + 2 * tig;
            *(float2*)&Es[row * BPAD + col]       = make_float2(acc[mi][j][0], acc[mi][j][1]);
            *(float2*)&Es[(row + 8) * BPAD + col] = make_float2(acc[mi][j][2], acc[mi][j][3]);
        }
    __syncthreads();

    int rr = tid >> 2;                 // 0..63
    int r  = row0 + rr;
    int cb = (tid & 3) * 16;           // 0,16,32,48
    if (r < rend) {
        float* dst = g_act + (size_t)r * I_DIM + col0g + cb;
        #pragma unroll
        for (int jj = 0; jj < 16; jj += 4) {
            float4 gv = *(float4*)&Es[rr * BPAD + cb + jj];
            float4 uv = *(float4*)&Es[rr * BPAD + 64 + cb + jj];
            float4 o;
            o.x = tfr(gv.x * (1.0f / (1.0f + __expf(-gv.x))) * uv.x);
            o.y = tfr(gv.y * (1.0f / (1.0f + __expf(-gv.y))) * uv.y);
            o.z = tfr(gv.z * (1.0f / (1.0f + __expf(-gv.z))) * uv.z);
            o.w = tfr(gv.w * (1.0f / (1.0f + __expf(-gv.w))) * uv.w);
            *(float4*)(dst + jj) = o;
        }
    }
}

// ---------------- GEMM2: fc2 = act @ W2[e], tf32 mma.sync ----------------
// Block: 64 rows x 128 cols. Warps 2x4, warp tile 32x32.
__global__ void __launch_bounds__(256, 3)
gemm2_kernel(const float* __restrict__ w2) {
    extern __shared__ char smem[];
    uint32_t sb = s2u(smem);
    int mt = blockIdx.x;
    if (mt >= g_num_tiles) return;
    int e = g_tile_expert[mt], row0 = g_tile_row[mt], rend = g_tile_end[mt];
    int col0 = blockIdx.y * 128;

    int tid = threadIdx.x, lane = tid & 31, wid = tid >> 5;
    int warpM = wid >> 2, warpN = wid & 3;
    int gid = lane >> 2, tig = lane & 3;

    const float* W = w2 + (size_t)e * I_DIM * H_DIM;
    int am = tid >> 2;
    int ac0 = (tid & 3) * 2;
    int akey = am & 7;
    int rrow = row0 + am; if (rrow >= NROWS) rrow = NROWS - 1;   // clamp; masked later
    const float* asrc = g_act + (size_t)rrow * I_DIM;

    auto load_chunk = [&](int ci, int buf) {
        int k0 = ci * 32;
        uint32_t Ab = sb + OFF_A(buf);
        cp16(Ab + am * 128 + ((ac0 ^ akey) << 4),       asrc + k0 + ac0 * 4, 16);
        cp16(Ab + am * 128 + (((ac0 + 1) ^ akey) << 4), asrc + k0 + ac0 * 4 + 4, 16);
        uint32_t Bb = sb + OFF_B(buf);
        #pragma unroll
        for (int it = 0; it < 4; it++) {
            int q = tid + it * 256;
            int k = q >> 5, c16 = q & 31, n = c16 * 4;
            cp16(Bb + k * (BPAD * 4) + n * 4, W + (size_t)(k0 + k) * H_DIM + col0 + n, 16);
        }
        cp_commit();
    };

    int mlane = lane & 15, extra = lane >> 4, key = lane & 7;
    int boff = tig * BPAD + warpN * 32 + gid;

    float acc[2][4][4] = {};
    const int NC = I_DIM / 32;   // 24
    load_chunk(0, 0);
    load_chunk(1, 1);
    int bc = 0;
    for (int i = 0; i < NC; i++) {
        cp_wait<1>();
        __syncthreads();
        int bn = bc + 2; if (bn >= 3) bn -= 3;
        if (i + 2 < NC) load_chunk(i + 2, bn);
        else            cp_commit();

        uint32_t Ab = sb + OFF_A(bc);
        const float* Bsp = (const float*)(smem + OFF_B(bc));
        #pragma unroll
        for (int ks = 0; ks < 4; ks++) {
            uint32_t a[2][4];
            #pragma unroll
            for (int mi = 0; mi < 2; mi++) {
                uint32_t addr = Ab + (uint32_t)((warpM * 32 + mi * 16 + mlane) * 128
                              + ((((ks << 1) | extra) ^ key) << 4));
                ldsm4(a[mi], addr);
            }
            #pragma unroll
            for (int j = 0; j < 4; j++) {
                uint32_t b0 = f2tf_f(Bsp[boff + ks * (8 * BPAD) + j * 8]);
                uint32_t b1 = f2tf_f(Bsp[boff + ks * (8 * BPAD) + j * 8 + 4 * BPAD]);
                mma8(acc[0][j], a[0], b0, b1);
                mma8(acc[1][j], a[1], b0, b1);
            }
        }
        bc = (bc + 1 == 3) ? 0 : bc + 1;
    }

    // epilogue: direct to g_fc2
    #pragma unroll
    for (int mi = 0; mi < 2; mi++) {
        int row = row0 + warpM * 32 + mi * 16 + gid;
        #pragma unroll
        for (int j = 0; j < 4; j++) {
            int col = col0 + warpN * 32 + j * 8 + 2 * tig;
            if (row < rend)
                *(float2*)&g_fc2[(size_t)row * H_DIM + col] =
                    make_float2(acc[mi][j][0], acc[mi][j][1]);
            if (row + 8 < rend)
                *(float2*)&g_fc2[(size_t)(row + 8) * H_DIM + col] =
                    make_float2(acc[mi][j][2], acc[mi][j][3]);
        }
    }
}

// ---------------- combine ----------------
__global__ void __launch_bounds__(256)
combine_kernel(const float* __restrict__ rw, float* __restrict__ out) {
    int i = blockIdx.x * blockDim.x + threadIdx.x;
    if (i >= T_TOK * (H_DIM / 4)) return;
    int t  = i >> 9;
    int h4 = i & 511;
    int p0 = g_pos[2 * t];
    int p1 = g_pos[2 * t + 1];
    float w0 = rw[2 * t];
    float w1 = rw[2 * t + 1];
    float4 v0 = *reinterpret_cast<const float4*>(&g_fc2[(size_t)p0 * H_DIM + h4 * 4]);
    float4 v1 = *reinterpret_cast<const float4*>(&g_fc2[(size_t)p1 * H_DIM + h4 * 4]);
    float4 o;
    o.x = w0 * v0.x + w1 * v1.x;
    o.y = w0 * v0.y + w1 * v1.y;
    o.z = w0 * v0.z + w1 * v1.z;
    o.w = w0 * v0.w + w1 * v1.w;
    reinterpret_cast<float4*>(out)[i] = o;
}

// ---------------- launch ----------------
extern "C" void kernel_launch(void* const* d_in, const int* in_sizes, int n_in,
                              void* d_out, int out_size) {
    const float* x   = (const float*)d_in[0];   // hidden_states [T, H]
    const float* rw  = (const float*)d_in[1];   // routing_weights [T, K]
    const float* w1  = (const float*)d_in[2];   // gate_up_proj [E, H, 2I]
    const float* w2  = (const float*)d_in[3];   // down_proj   [E, I, H]
    const int*   sel = (const int*)d_in[4];     // selected_experts [T, K]
    float* out = (float*)d_out;                 // [T, H] fp32

    cudaFuncSetAttribute(gemm1_kernel, cudaFuncAttributeMaxDynamicSharedMemorySize, SMEM_TOTAL);
    cudaFuncSetAttribute(gemm2_kernel, cudaFuncAttributeMaxDynamicSharedMemorySize, SMEM_TOTAL);

    setup_kernel<<<1, 256>>>(sel);
    cvtx_kernel<<<(T_TOK * H_DIM / 4 + 255) / 256, 256>>>(x);
    gemm1_kernel<<<dim3(MAX_TILES, I_DIM / 64), 256, SMEM_TOTAL>>>(w1);
    gemm2_kernel<<<dim3(MAX_TILES, H_DIM / 128), 256, SMEM_TOTAL>>>(w2);
    combine_kernel<<<(T_TOK * H_DIM / 4 + 255) / 256, 256>>>(rw, out);
}